// round 6
// baseline (speedup 1.0000x reference)
#include <cuda_runtime.h>
#include <math.h>
#include <stdint.h>

// Problem constants
#define BB     4
#define SEQ_N  1024
#define SEQ_M  2048
#define CH     768
#define NH     12
#define HD     64
#define QSCALE 0.125f
#define NEGV   -9e15f

// Scratch (device globals: allocation-free rule)
__device__ __align__(256) float g_Qp[BB*NH*SEQ_N*HD];   // [B,H,N,d] pre-scaled fp32
__device__ __align__(256) float g_K [BB*NH*SEQ_M*HD];   // [B,H,M,d]
__device__ __align__(256) float g_V [BB*NH*SEQ_M*HD];   // [B,H,M,d]
__device__ __align__(256) float g_X [BB*SEQ_N*CH];      // attention out [B,N,C]

// ---------------------------------------------------------------------------
// tf32 helpers. Values in smem are pre-split: float2(hi, lo).
// ---------------------------------------------------------------------------
__device__ __forceinline__ uint32_t f2tf(float x) {
    uint32_t r; asm("cvt.rna.tf32.f32 %0, %1;" : "=r"(r) : "f"(x)); return r;
}
__device__ __forceinline__ float2 splitF(float x) {
    float h = __uint_as_float(f2tf(x));
    float l = __uint_as_float(f2tf(x - h));
    return make_float2(h, l);
}
__device__ __forceinline__ void mma8(float* c, const uint32_t* a, const uint32_t* b) {
    asm volatile(
        "mma.sync.aligned.m16n8k8.row.col.f32.tf32.tf32.f32 "
        "{%0,%1,%2,%3}, {%4,%5,%6,%7}, {%8,%9}, {%0,%1,%2,%3};"
        : "+f"(c[0]), "+f"(c[1]), "+f"(c[2]), "+f"(c[3])
        : "r"(a[0]), "r"(a[1]), "r"(a[2]), "r"(a[3]), "r"(b[0]), "r"(b[1]));
}
// 3xTF32: c += a_hi*b_hi + a_hi*b_lo + a_lo*b_hi   (a: 4 float2, b: 2 float2)
__device__ __forceinline__ void mma3f(float* c, const float2* a, const float2* b) {
    uint32_t ah[4] = {__float_as_uint(a[0].x), __float_as_uint(a[1].x),
                      __float_as_uint(a[2].x), __float_as_uint(a[3].x)};
    uint32_t al[4] = {__float_as_uint(a[0].y), __float_as_uint(a[1].y),
                      __float_as_uint(a[2].y), __float_as_uint(a[3].y)};
    uint32_t bh[2] = {__float_as_uint(b[0].x), __float_as_uint(b[1].x)};
    uint32_t bl[2] = {__float_as_uint(b[0].y), __float_as_uint(b[1].y)};
    mma8(c, ah, bh);
    mma8(c, ah, bl);
    mma8(c, al, bh);
}

// ---------------------------------------------------------------------------
// Projection GEMM core: out[r,o] = sum_k A[r,k]*W[o,k], K = 768.
// Block 128(m) x 64(n), 256 thr = 8 warps (4m x 2n). BK = 16.
// smem tiles are k-major (col-major) pre-split float2:
//   A: elem(r,k) at AHL[k*PA + r], PA = 132 (== 4 mod 16 -> conflict-free frags)
//   W: elem(o,k) at WHL[k*PW + o], PW = 68
// Single smem buffer; next tile's gmem loads staged in registers.
// ---------------------------------------------------------------------------
#define PA 132
#define PW 68

__device__ __forceinline__ void gemm_core(const float* __restrict__ A,
                                          const float* __restrict__ W,
                                          int rowBase, int oBase,
                                          float2* __restrict__ AHL,
                                          float2* __restrict__ WHL,
                                          float acc[2][4][4])
{
    const int tid  = threadIdx.x;
    const int warp = tid >> 5, lane = tid & 31;
    const int wm = warp >> 1, wn = warp & 1;
    const int g  = lane >> 2, tg = lane & 3;

    // Loader geometry (lanes span 32 rows -> conflict-free col-major STS.64)
    const int ar = tid & 127, ahalf = tid >> 7;     // A: 1 row, 8 cols
    const int wr = tid & 63,  wq    = tid >> 6;     // W: 1 row, 4 cols
    const float* aSrc = A + (size_t)(rowBase + ar) * CH + ahalf * 8;
    const float* wSrc = W + (size_t)(oBase + wr) * CH + wq * 4;

    float4 ra0 = *(const float4*)(aSrc);
    float4 ra1 = *(const float4*)(aSrc + 4);
    float4 rw  = *(const float4*)(wSrc);

#pragma unroll 1
    for (int kt = 0; kt < CH; kt += 16) {
        {   // stage current tile (split once here)
            float2* Ad = AHL + ar + ahalf * 8 * PA;
            Ad[0*PA] = splitF(ra0.x); Ad[1*PA] = splitF(ra0.y);
            Ad[2*PA] = splitF(ra0.z); Ad[3*PA] = splitF(ra0.w);
            Ad[4*PA] = splitF(ra1.x); Ad[5*PA] = splitF(ra1.y);
            Ad[6*PA] = splitF(ra1.z); Ad[7*PA] = splitF(ra1.w);
            float2* Wd = WHL + wr + wq * 4 * PW;
            Wd[0*PW] = splitF(rw.x); Wd[1*PW] = splitF(rw.y);
            Wd[2*PW] = splitF(rw.z); Wd[3*PW] = splitF(rw.w);
        }
        __syncthreads();
        if (kt + 16 < CH) {   // prefetch next tile into regs (covered by compute)
            ra0 = *(const float4*)(aSrc + kt + 16);
            ra1 = *(const float4*)(aSrc + kt + 20);
            rw  = *(const float4*)(wSrc + kt + 16);
        }
#pragma unroll
        for (int k8 = 0; k8 < 16; k8 += 8) {
            float2 af[2][4];
#pragma unroll
            for (int mi = 0; mi < 2; mi++) {
                const float2* bA = AHL + (k8 + tg) * PA + wm * 32 + mi * 16 + g;
                af[mi][0] = bA[0];          // (row g,   col tg)
                af[mi][1] = bA[8];          // (row g+8, col tg)
                af[mi][2] = bA[4 * PA];     // (row g,   col tg+4)
                af[mi][3] = bA[4 * PA + 8]; // (row g+8, col tg+4)
            }
            float2 wf[4][2];
#pragma unroll
            for (int nj = 0; nj < 4; nj++) {
                const float2* bW = WHL + (k8 + tg) * PW + wn * 32 + nj * 8 + g;
                wf[nj][0] = bW[0];
                wf[nj][1] = bW[4 * PW];
            }
#pragma unroll
            for (int mi = 0; mi < 2; mi++)
#pragma unroll
                for (int nj = 0; nj < 4; nj++)
                    mma3f(acc[mi][nj], af[mi], wf[nj]);
        }
        __syncthreads();
    }
}

// ---------------------------------------------------------------------------
// Fused Q + KV projection (one launch, 384 + 1536 = 1920 blocks)
// ---------------------------------------------------------------------------
__global__ __launch_bounds__(256)
void qkv_gemm(const float* __restrict__ q, const float* __restrict__ kvin,
              const float* __restrict__ Wq, const float* __restrict__ Wkv)
{
    __shared__ float2 AHL[16 * PA];
    __shared__ float2 WHL[16 * PW];

    const int tid  = threadIdx.x;
    const int warp = tid >> 5, lane = tid & 31;
    const int wm = warp >> 1, wn = warp & 1;
    const int g  = lane >> 2, tg = lane & 3;

    float acc[2][4][4];
#pragma unroll
    for (int mi = 0; mi < 2; mi++)
#pragma unroll
        for (int nj = 0; nj < 4; nj++)
#pragma unroll
            for (int t = 0; t < 4; t++) acc[mi][nj][t] = 0.f;

    int id = blockIdx.x;
    if (id < 384) {
        // -------- Q projection: rows 4096, cols 768 --------
        const int bx = id % 12, by = id / 12;
        const int rowBase = by * 128;
        gemm_core(q, Wq, rowBase, bx * 64, AHL, WHL, acc);
        const int h = bx;                       // 64-wide n-tile == one head
#pragma unroll
        for (int mi = 0; mi < 2; mi++) {
            const int r0 = rowBase + wm * 32 + mi * 16 + g;
            const int r1 = r0 + 8;
            const int b0 = r0 >> 10, n0_ = r0 & 1023;
            const int b1 = r1 >> 10, n1_ = r1 & 1023;
#pragma unroll
            for (int nj = 0; nj < 4; nj++) {
                float* cc = acc[mi][nj];
                const int colLoc = wn * 32 + nj * 8 + tg * 2;
                *(float2*)&g_Qp[(((size_t)(b0*NH + h)*SEQ_N + n0_) << 6) + colLoc] =
                    make_float2(cc[0] * QSCALE, cc[1] * QSCALE);
                *(float2*)&g_Qp[(((size_t)(b1*NH + h)*SEQ_N + n1_) << 6) + colLoc] =
                    make_float2(cc[2] * QSCALE, cc[3] * QSCALE);
            }
        }
    } else {
        // -------- KV projection: rows 8192, cols 1536 --------
        id -= 384;
        const int bx = id % 24, by = id / 24;
        const int rowBase = by * 128;
        gemm_core(kvin, Wkv, rowBase, bx * 64, AHL, WHL, acc);
        float* dst = (bx >= NH) ? g_V : g_K;
        const int h = bx % NH;
#pragma unroll
        for (int mi = 0; mi < 2; mi++) {
            const int r0 = rowBase + wm * 32 + mi * 16 + g;
            const int r1 = r0 + 8;
            const int b0 = r0 >> 11, m0_ = r0 & 2047;
            const int b1 = r1 >> 11, m1_ = r1 & 2047;
#pragma unroll
            for (int nj = 0; nj < 4; nj++) {
                float* cc = acc[mi][nj];
                const int colLoc = wn * 32 + nj * 8 + tg * 2;
                *(float2*)&dst[(((size_t)(b0*NH + h)*SEQ_M + m0_) << 6) + colLoc] =
                    make_float2(cc[0], cc[1]);
                *(float2*)&dst[(((size_t)(b1*NH + h)*SEQ_M + m1_) << 6) + colLoc] =
                    make_float2(cc[2], cc[3]);
            }
        }
    }
}

// ---------------------------------------------------------------------------
// Output projection + bias (A = g_X)
// ---------------------------------------------------------------------------
__global__ __launch_bounds__(256)
void out_gemm(const float* __restrict__ Wproj, const float* __restrict__ bias,
              float* __restrict__ out)
{
    __shared__ float2 AHL[16 * PA];
    __shared__ float2 WHL[16 * PW];

    const int tid  = threadIdx.x;
    const int warp = tid >> 5, lane = tid & 31;
    const int wm = warp >> 1, wn = warp & 1;
    const int g  = lane >> 2, tg = lane & 3;
    const int rowBase = blockIdx.y * 128;
    const int oBase   = blockIdx.x * 64;

    float acc[2][4][4];
#pragma unroll
    for (int mi = 0; mi < 2; mi++)
#pragma unroll
        for (int nj = 0; nj < 4; nj++)
#pragma unroll
            for (int t = 0; t < 4; t++) acc[mi][nj][t] = 0.f;

    gemm_core(g_X, Wproj, rowBase, oBase, AHL, WHL, acc);

#pragma unroll
    for (int mi = 0; mi < 2; mi++) {
        const int r0 = rowBase + wm * 32 + mi * 16 + g;
        const int r1 = r0 + 8;
#pragma unroll
        for (int nj = 0; nj < 4; nj++) {
            float* cc = acc[mi][nj];
            const int col = oBase + wn * 32 + nj * 8 + tg * 2;
            float2 bi = *(const float2*)(bias + col);
            *(float2*)&out[(size_t)r0 * CH + col] = make_float2(cc[0] + bi.x, cc[1] + bi.y);
            *(float2*)&out[(size_t)r1 * CH + col] = make_float2(cc[2] + bi.x, cc[3] + bi.y);
        }
    }
}

// ---------------------------------------------------------------------------
// Flash attention. 128 thr = 4 warps x 16 q-rows. Pre-split smem:
//   Ks: elem(n,k) at Ks[k*PK + n]   (k-major)  -> S B-frag reads conflict-free
//   Vs: elem(m,d) at Vs[d*PK + m]   (d-major)  -> PV B-frag reads conflict-free
//   Ps: elem(n,m) at Ps[n*PK + m]   (row-major)
// Q fragments split once into registers. grid = (N/64, B*H)
// ---------------------------------------------------------------------------
#define PK 68
#define FA_SMEM (3 * 64 * PK * (int)sizeof(float2))   // 104448 B

__global__ __launch_bounds__(128)
void flash_mma(const int* __restrict__ mask)
{
    extern __shared__ float2 smf[];
    float2* Ks = smf;
    float2* Vs = smf + 64 * PK;
    float2* Ps = smf + 2 * 64 * PK;

    const int tid  = threadIdx.x;
    const int warp = tid >> 5, lane = tid & 31;
    const int g = lane >> 2, tg = lane & 3;
    const int bh = blockIdx.y, b = bh / NH, h = bh % NH;
    const int n0 = blockIdx.x * 64;
    const int rb = warp * 16;

    // Q fragments straight from gmem (one-time), split into registers
    const float* Qg = g_Qp + ((size_t)bh * SEQ_N + n0 + rb) * HD;
    float2 qf[8][4];
#pragma unroll
    for (int k8 = 0; k8 < 8; k8++) {
        qf[k8][0] = splitF(Qg[(g    ) * HD + k8*8 + tg    ]);
        qf[k8][1] = splitF(Qg[(g + 8) * HD + k8*8 + tg    ]);
        qf[k8][2] = splitF(Qg[(g    ) * HD + k8*8 + tg + 4]);
        qf[k8][3] = splitF(Qg[(g + 8) * HD + k8*8 + tg + 4]);
    }

    float m0 = -INFINITY, m1 = -INFINITY, l0 = 0.f, l1 = 0.f;
    float o[8][4];
#pragma unroll
    for (int nj = 0; nj < 8; nj++)
#pragma unroll
        for (int t = 0; t < 4; t++) o[nj][t] = 0.f;

    const int* mrow0 = mask + ((size_t)b * SEQ_N + n0 + rb + g) * SEQ_M;
    const int* mrow1 = mrow0 + (size_t)8 * SEQ_M;
    const float* Kg = g_K + (size_t)bh * SEQ_M * HD;
    const float* Vg = g_V + (size_t)bh * SEQ_M * HD;

#pragma unroll 1
    for (int mt = 0; mt < SEQ_M; mt += 64) {
        __syncthreads();   // previous PV done before K/V overwrite
        for (int idx = tid; idx < 1024; idx += 128) {
            const int r = idx & 63, cg = idx >> 6;        // 32 rows per warp phase
            const float4 kx = *(const float4*)(Kg + (size_t)(mt + r) * HD + cg * 4);
            const float4 vx = *(const float4*)(Vg + (size_t)(mt + r) * HD + cg * 4);
            float2* kd = Ks + (cg * 4) * PK + r;
            kd[0*PK] = splitF(kx.x); kd[1*PK] = splitF(kx.y);
            kd[2*PK] = splitF(kx.z); kd[3*PK] = splitF(kx.w);
            float2* vd = Vs + (cg * 4) * PK + r;
            vd[0*PK] = splitF(vx.x); vd[1*PK] = splitF(vx.y);
            vd[2*PK] = splitF(vx.z); vd[3*PK] = splitF(vx.w);
        }
        __syncthreads();

        // S = Q @ K^T  (per warp: 16 rows x 64 cols)
        float s[8][4];
#pragma unroll
        for (int nj = 0; nj < 8; nj++)
#pragma unroll
            for (int t = 0; t < 4; t++) s[nj][t] = 0.f;

#pragma unroll
        for (int k8 = 0; k8 < 8; k8++) {
#pragma unroll
            for (int nj = 0; nj < 8; nj++) {
                const float2* bK = Ks + (k8*8 + tg) * PK + nj*8 + g;
                float2 kf[2] = { bK[0], bK[4 * PK] };
                mma3f(s[nj], qf[k8], kf);
            }
        }

        // mask
#pragma unroll
        for (int nj = 0; nj < 8; nj++) {
            int2 mk0 = *(const int2*)(mrow0 + mt + nj*8 + tg*2);
            int2 mk1 = *(const int2*)(mrow1 + mt + nj*8 + tg*2);
            if (!mk0.x) s[nj][0] = NEGV;
            if (!mk0.y) s[nj][1] = NEGV;
            if (!mk1.x) s[nj][2] = NEGV;
            if (!mk1.y) s[nj][3] = NEGV;
        }

        // online softmax (rows live in 4 lanes: shfl over lanes 1,2)
        float tm0 = -INFINITY, tm1 = -INFINITY;
#pragma unroll
        for (int nj = 0; nj < 8; nj++) {
            tm0 = fmaxf(tm0, fmaxf(s[nj][0], s[nj][1]));
            tm1 = fmaxf(tm1, fmaxf(s[nj][2], s[nj][3]));
        }
        tm0 = fmaxf(tm0, __shfl_xor_sync(0xffffffffu, tm0, 1));
        tm0 = fmaxf(tm0, __shfl_xor_sync(0xffffffffu, tm0, 2));
        tm1 = fmaxf(tm1, __shfl_xor_sync(0xffffffffu, tm1, 1));
        tm1 = fmaxf(tm1, __shfl_xor_sync(0xffffffffu, tm1, 2));
        float mn0 = fmaxf(m0, tm0), mn1 = fmaxf(m1, tm1);
        float c0 = __expf(m0 - mn0), c1 = __expf(m1 - mn1);
        float ts0 = 0.f, ts1 = 0.f;
#pragma unroll
        for (int nj = 0; nj < 8; nj++) {
            float p0 = __expf(s[nj][0] - mn0), p1 = __expf(s[nj][1] - mn0);
            float p2 = __expf(s[nj][2] - mn1), p3 = __expf(s[nj][3] - mn1);
            ts0 += p0 + p1; ts1 += p2 + p3;
            float2* pr0 = Ps + (rb + g    ) * PK + nj*8 + 2*tg;
            float2* pr1 = Ps + (rb + g + 8) * PK + nj*8 + 2*tg;
            pr0[0] = splitF(p0); pr0[1] = splitF(p1);
            pr1[0] = splitF(p2); pr1[1] = splitF(p3);
        }
        ts0 += __shfl_xor_sync(0xffffffffu, ts0, 1);
        ts0 += __shfl_xor_sync(0xffffffffu, ts0, 2);
        ts1 += __shfl_xor_sync(0xffffffffu, ts1, 1);
        ts1 += __shfl_xor_sync(0xffffffffu, ts1, 2);
        l0 = l0 * c0 + ts0; m0 = mn0;
        l1 = l1 * c1 + ts1; m1 = mn1;
#pragma unroll
        for (int nj = 0; nj < 8; nj++) {
            o[nj][0] *= c0; o[nj][1] *= c0;
            o[nj][2] *= c1; o[nj][3] *= c1;
        }
        __syncwarp();   // P rows are warp-private; make stores visible in-warp

        // O += P @ V
#pragma unroll
        for (int k8 = 0; k8 < 8; k8++) {
            const float2* bP = Ps + (rb + g) * PK + k8*8 + tg;
            float2 paf[4] = { bP[0], bP[8 * PK], bP[4], bP[8 * PK + 4] };
#pragma unroll
            for (int nj = 0; nj < 8; nj++) {
                const float2* bV = Vs + (nj*8 + g) * PK + k8*8 + tg;
                float2 vf[2] = { bV[0], bV[4] };
                mma3f(o[nj], paf, vf);
            }
        }
    }

    // normalize + write X[b, n, h*64 + d]
    float inv0 = 1.f / l0, inv1 = 1.f / l1;
    float* X0 = g_X + ((size_t)b * SEQ_N + n0 + rb + g) * CH + h * HD;
    float* X1 = X0 + (size_t)8 * CH;
#pragma unroll
    for (int nj = 0; nj < 8; nj++) {
        *(float2*)(X0 + nj*8 + tg*2) = make_float2(o[nj][0]*inv0, o[nj][1]*inv0);
        *(float2*)(X1 + nj*8 + tg*2) = make_float2(o[nj][2]*inv1, o[nj][3]*inv1);
    }
}

// ---------------------------------------------------------------------------
extern "C" void kernel_launch(void* const* d_in, const int* in_sizes, int n_in,
                              void* d_out, int out_size)
{
    const float* q     = (const float*)d_in[0];   // [4,1024,768]
    const float* kv    = (const float*)d_in[1];   // [4,2048,768]
    const float* Wq    = (const float*)d_in[2];   // [768,768]
    const float* Wkv   = (const float*)d_in[3];   // [1536,768]
    const float* Wproj = (const float*)d_in[4];   // [768,768]
    const float* bproj = (const float*)d_in[5];   // [768]
    const int*   mask  = (const int*)d_in[6];     // [4,1,1024,2048]
    float* out = (float*)d_out;                   // [4,1024,768]

    cudaFuncSetAttribute(flash_mma,
                         cudaFuncAttributeMaxDynamicSharedMemorySize, FA_SMEM);

    // Fused Q + KV projections (384 + 1536 blocks)
    qkv_gemm<<<1920, 256>>>(q, kv, Wq, Wkv);
    // Fused masked-softmax attention
    flash_mma<<<dim3(SEQ_N/64, BB*NH), 128, FA_SMEM>>>(mask);
    // Output projection + bias
    out_gemm<<<dim3(CH/64, (BB*SEQ_N)/128), 256>>>(Wproj, bproj, out);
}

// round 7
// speedup vs baseline: 1.3001x; 1.3001x over previous
#include <cuda_runtime.h>
#include <cuda_bf16.h>
#include <math.h>
#include <stdint.h>

// Problem constants
#define BB     4
#define SEQ_N  1024
#define SEQ_M  2048
#define CH     768
#define NH     12
#define HD     64
#define QSCALE 0.125f
#define NEGV   -9e15f

// Scratch (device globals: allocation-free rule)
__device__ __align__(256) float g_Qp[BB*NH*SEQ_N*HD];   // [B,H,N,d] pre-scaled
__device__ __align__(256) float g_K [BB*NH*SEQ_M*HD];   // [B,H,M,d]
__device__ __align__(256) float g_V [BB*NH*SEQ_M*HD];   // [B,H,M,d]
__device__ __align__(256) float g_X [BB*SEQ_N*CH];      // attention out [B,N,C]

// ---------------------------------------------------------------------------
// bf16 helpers. pack_bf2(x0,x1): x0 -> bits[15:0] (lower k), x1 -> bits[31:16].
// split2: 3xBF16 decomposition of a k-pair into (hi, lo) packed words.
// ---------------------------------------------------------------------------
__device__ __forceinline__ uint32_t pack_bf2(float x0, float x1) {
    uint32_t r;
    asm("cvt.rn.bf16x2.f32 %0, %1, %2;" : "=r"(r) : "f"(x1), "f"(x0));
    return r;
}
__device__ __forceinline__ void split2(float x0, float x1, uint32_t& hi, uint32_t& lo) {
    hi = pack_bf2(x0, x1);
    float h0 = __uint_as_float(hi << 16);
    float h1 = __uint_as_float(hi & 0xffff0000u);
    lo = pack_bf2(x0 - h0, x1 - h1);
}
__device__ __forceinline__ void mma16(float* c, const uint32_t* a, const uint32_t* b) {
    asm volatile(
        "mma.sync.aligned.m16n8k16.row.col.f32.bf16.bf16.f32 "
        "{%0,%1,%2,%3}, {%4,%5,%6,%7}, {%8,%9}, {%0,%1,%2,%3};"
        : "+f"(c[0]), "+f"(c[1]), "+f"(c[2]), "+f"(c[3])
        : "r"(a[0]), "r"(a[1]), "r"(a[2]), "r"(a[3]), "r"(b[0]), "r"(b[1]));
}
// c += ah*bh + ah*bl + al*bh
__device__ __forceinline__ void mma3(float* c, const uint32_t* ah, const uint32_t* al,
                                     const uint32_t* bh, const uint32_t* bl) {
    mma16(c, ah, bh);
    mma16(c, ah, bl);
    mma16(c, al, bh);
}

// ---------------------------------------------------------------------------
// Projection GEMM: out[r,o] = sum_k A[r,k]*W[o,k], K=768, BK=16 (1 mma k-step).
// Block 128m x 64n, 8 warps (4m x 2n). smem: bf16 hi/lo planes, row-major,
// 8 words/row (pair-interleaved: word 2t holds k-pair t, word 2t+1 pair t+4)
// -> fragment loads are single LDS.64, conflict-free (pitch 8: 8g+2tg bijection
//    over each 16-lane phase).
// mode 0: Q proj (*QSCALE -> g_Qp)  1: KV proj (-> g_K/g_V)  2: out proj (+bias)
// ---------------------------------------------------------------------------
__global__ __launch_bounds__(256)
void gemm_bf(const float* __restrict__ Ain, const float* __restrict__ W,
             int mode, float* __restrict__ out, const float* __restrict__ bias)
{
    __shared__ uint32_t Ahi[128*8], Alo[128*8];
    __shared__ uint32_t Whi[64*8],  Wlo[64*8];

    const int tid  = threadIdx.x;
    const int warp = tid >> 5, lane = tid & 31;
    const int wm = warp >> 1, wn = warp & 1;
    const int g  = lane >> 2, tg = lane & 3;
    const int rowBase = blockIdx.y * 128;
    const int oBase   = blockIdx.x * 64;
    const float* A = (mode == 2) ? g_X : Ain;

    // loaders: A = 1 row x 8 k per thread; W = 1 row x 4 k per thread
    const int ar = tid >> 1, ah_ = tid & 1;
    const int wr = tid & 63, wq  = tid >> 6;
    const float* aSrc = A + (size_t)(rowBase + ar) * CH + ah_ * 8;
    const float* wSrc = W + (size_t)(oBase + wr) * CH + wq * 4;
    const int wp0 = 2 * wq;
    const int ww0 = 2 * (wp0 & 3) + (wp0 >> 2);
    const int ww1 = 2 * ((wp0 + 1) & 3) + ((wp0 + 1) >> 2);

    float4 ra0 = *(const float4*)(aSrc);
    float4 ra1 = *(const float4*)(aSrc + 4);
    float4 rw  = *(const float4*)(wSrc);

    float acc[2][4][4];
#pragma unroll
    for (int mi = 0; mi < 2; mi++)
#pragma unroll
        for (int nj = 0; nj < 4; nj++)
#pragma unroll
            for (int t = 0; t < 4; t++) acc[mi][nj][t] = 0.f;

#pragma unroll 1
    for (int kt = 0; kt < CH; kt += 16) {
        {   // stage current tile (split once)
            uint32_t h, l;
            float av[8] = {ra0.x, ra0.y, ra0.z, ra0.w, ra1.x, ra1.y, ra1.z, ra1.w};
            uint32_t* Ad_h = Ahi + ar * 8 + ah_;
            uint32_t* Ad_l = Alo + ar * 8 + ah_;
#pragma unroll
            for (int j = 0; j < 4; j++) {
                split2(av[2*j], av[2*j+1], h, l);
                Ad_h[2*j] = h; Ad_l[2*j] = l;
            }
            split2(rw.x, rw.y, h, l); Whi[wr*8 + ww0] = h; Wlo[wr*8 + ww0] = l;
            split2(rw.z, rw.w, h, l); Whi[wr*8 + ww1] = h; Wlo[wr*8 + ww1] = l;
        }
        __syncthreads();
        if (kt + 16 < CH) {
            ra0 = *(const float4*)(aSrc + kt + 16);
            ra1 = *(const float4*)(aSrc + kt + 20);
            rw  = *(const float4*)(wSrc + kt + 16);
        }
        // fragments: one LDS.64 per (row, plane)
        uint32_t Ah[2][4], Al[2][4];
#pragma unroll
        for (int mi = 0; mi < 2; mi++) {
            const int r = (wm * 32 + mi * 16 + g) * 8 + 2 * tg;
            uint2 h0 = *(const uint2*)&Ahi[r], h1 = *(const uint2*)&Ahi[r + 64];
            uint2 l0 = *(const uint2*)&Alo[r], l1 = *(const uint2*)&Alo[r + 64];
            Ah[mi][0] = h0.x; Ah[mi][1] = h1.x; Ah[mi][2] = h0.y; Ah[mi][3] = h1.y;
            Al[mi][0] = l0.x; Al[mi][1] = l1.x; Al[mi][2] = l0.y; Al[mi][3] = l1.y;
        }
        uint32_t Bh[4][2], Bl[4][2];
#pragma unroll
        for (int nj = 0; nj < 4; nj++) {
            const int r = (wn * 32 + nj * 8 + g) * 8 + 2 * tg;
            uint2 hv = *(const uint2*)&Whi[r];
            uint2 lv = *(const uint2*)&Wlo[r];
            Bh[nj][0] = hv.x; Bh[nj][1] = hv.y;
            Bl[nj][0] = lv.x; Bl[nj][1] = lv.y;
        }
#pragma unroll
        for (int mi = 0; mi < 2; mi++)
#pragma unroll
            for (int nj = 0; nj < 4; nj++)
                mma3(acc[mi][nj], Ah[mi], Al[mi], Bh[nj], Bl[nj]);
        __syncthreads();
    }

    // Epilogue
#pragma unroll
    for (int mi = 0; mi < 2; mi++) {
        const int r0 = rowBase + wm * 32 + mi * 16 + g;
        const int r1 = r0 + 8;
#pragma unroll
        for (int nj = 0; nj < 4; nj++) {
            float* cc = acc[mi][nj];
            const int colLoc = wn * 32 + nj * 8 + tg * 2;
            if (mode == 0) {
                const int h = blockIdx.x;
                const int b0 = r0 >> 10, n0_ = r0 & 1023;
                const int b1 = r1 >> 10, n1_ = r1 & 1023;
                *(float2*)&g_Qp[(((size_t)(b0*NH + h)*SEQ_N + n0_) << 6) + colLoc] =
                    make_float2(cc[0]*QSCALE, cc[1]*QSCALE);
                *(float2*)&g_Qp[(((size_t)(b1*NH + h)*SEQ_N + n1_) << 6) + colLoc] =
                    make_float2(cc[2]*QSCALE, cc[3]*QSCALE);
            } else if (mode == 1) {
                const int bx = blockIdx.x;
                float* dst = (bx >= NH) ? g_V : g_K;
                const int h = bx % NH;
                const int b0 = r0 >> 11, m0_ = r0 & 2047;
                const int b1 = r1 >> 11, m1_ = r1 & 2047;
                *(float2*)&dst[(((size_t)(b0*NH + h)*SEQ_M + m0_) << 6) + colLoc] =
                    make_float2(cc[0], cc[1]);
                *(float2*)&dst[(((size_t)(b1*NH + h)*SEQ_M + m1_) << 6) + colLoc] =
                    make_float2(cc[2], cc[3]);
            } else {
                const int col = oBase + colLoc;
                float2 bi = *(const float2*)(bias + col);
                *(float2*)&out[(size_t)r0 * CH + col] = make_float2(cc[0]+bi.x, cc[1]+bi.y);
                *(float2*)&out[(size_t)r1 * CH + col] = make_float2(cc[2]+bi.x, cc[3]+bi.y);
            }
        }
    }
}

// ---------------------------------------------------------------------------
// Flash attention, bf16 3x. 128 thr = 4 warps x 16 q-rows.
// Ks/Vs: bf16 hi/lo planes, pair-interleaved per 16-k step, pitch 40 words
// (40 = 8 mod 32 -> frag LDS.64 conflict-free).
//   Ks row = m-index (S column), word = 8*step + pair-interleave(d)
//   Vs row = d (transposed at staging via bf16 half-word stores),
//            word = 8*step + pair-interleave(m), halfword = m&1
// P stays entirely in registers (thread's softmax regs == its PV A-fragment).
// grid = (N/64, B*H)
// ---------------------------------------------------------------------------
#define FPK 40

__global__ __launch_bounds__(128)
void flash_bf(const int* __restrict__ mask)
{
    __shared__ uint32_t Khi[64*FPK], Klo[64*FPK];
    __shared__ uint32_t Vhi[64*FPK], Vlo[64*FPK];

    const int tid  = threadIdx.x;
    const int warp = tid >> 5, lane = tid & 31;
    const int g = lane >> 2, tg = lane & 3;
    const int bh = blockIdx.y, b = bh / NH, h = bh % NH;
    const int n0 = blockIdx.x * 64;
    const int rb = warp * 16;

    // Q fragments from gmem, split once into registers
    uint32_t qh[4][4], ql[4][4];
    {
        const float* Qr0 = g_Qp + ((size_t)bh * SEQ_N + n0 + rb + g) * HD;
        const float* Qr1 = Qr0 + 8 * HD;
#pragma unroll
        for (int s = 0; s < 4; s++) {
            float2 x0 = *(const float2*)(Qr0 + 16*s + 2*tg);
            float2 x1 = *(const float2*)(Qr1 + 16*s + 2*tg);
            float2 x2 = *(const float2*)(Qr0 + 16*s + 8 + 2*tg);
            float2 x3 = *(const float2*)(Qr1 + 16*s + 8 + 2*tg);
            split2(x0.x, x0.y, qh[s][0], ql[s][0]);
            split2(x1.x, x1.y, qh[s][1], ql[s][1]);
            split2(x2.x, x2.y, qh[s][2], ql[s][2]);
            split2(x3.x, x3.y, qh[s][3], ql[s][3]);
        }
    }

    float m0 = -INFINITY, m1 = -INFINITY, l0 = 0.f, l1 = 0.f;
    float o[8][4];
#pragma unroll
    for (int nj = 0; nj < 8; nj++)
#pragma unroll
        for (int t = 0; t < 4; t++) o[nj][t] = 0.f;

    // staging geometry: thread = (row m = tid>>1, d-half = tid&1)
    const int smr = tid >> 1, shf = tid & 1;
    const int mq  = smr & 15;
    const int wv  = 8 * (smr >> 4) + 2 * ((mq >> 1) & 3) + (mq >> 3);
    const int vhalf = smr & 1;

    const int* mrow0 = mask + ((size_t)b * SEQ_N + n0 + rb + g) * SEQ_M;
    const int* mrow1 = mrow0 + (size_t)8 * SEQ_M;
    const float* Kg = g_K + (size_t)bh * SEQ_M * HD;
    const float* Vg = g_V + (size_t)bh * SEQ_M * HD;

#pragma unroll 1
    for (int mt = 0; mt < SEQ_M; mt += 64) {
        __syncthreads();   // previous PV reads done before overwrite
        {
            const float* krow = Kg + (size_t)(mt + smr) * HD + 32 * shf;
            const float* vrow = Vg + (size_t)(mt + smr) * HD + 32 * shf;
#pragma unroll
            for (int c = 0; c < 8; c++) {
                float4 kx = *(const float4*)(krow + 4*c);
                const int d0 = 32*shf + 4*c;
                const int st = d0 >> 4, p0 = (d0 & 15) >> 1;
                const int w0 = 8*st + 2*(p0 & 3) + (p0 >> 2);
                const int w1 = 8*st + 2*((p0+1) & 3) + ((p0+1) >> 2);
                uint32_t hh, ll;
                split2(kx.x, kx.y, hh, ll);
                Khi[smr*FPK + w0] = hh; Klo[smr*FPK + w0] = ll;
                split2(kx.z, kx.w, hh, ll);
                Khi[smr*FPK + w1] = hh; Klo[smr*FPK + w1] = ll;

                float4 vx = *(const float4*)(vrow + 4*c);
                const float* ve = &vx.x;
#pragma unroll
                for (int i = 0; i < 4; i++) {
                    float x = ve[i];
                    __nv_bfloat16 hb = __float2bfloat16(x);
                    __nv_bfloat16 lb = __float2bfloat16(x - __bfloat162float(hb));
                    const int idx = ((d0 + i) * FPK + wv) * 2 + vhalf;
                    ((__nv_bfloat16*)Vhi)[idx] = hb;
                    ((__nv_bfloat16*)Vlo)[idx] = lb;
                }
            }
        }
        __syncthreads();

        // S = Q @ K^T  (per warp: 16 rows x 64 cols)
        float s[8][4];
#pragma unroll
        for (int nj = 0; nj < 8; nj++)
#pragma unroll
            for (int t = 0; t < 4; t++) s[nj][t] = 0.f;

#pragma unroll
        for (int st = 0; st < 4; st++) {
#pragma unroll
            for (int nj = 0; nj < 8; nj++) {
                const int r = (nj*8 + g) * FPK + 8*st + 2*tg;
                uint2 hv = *(const uint2*)&Khi[r];
                uint2 lv = *(const uint2*)&Klo[r];
                uint32_t bhv[2] = {hv.x, hv.y}, blv[2] = {lv.x, lv.y};
                mma3(s[nj], qh[st], ql[st], bhv, blv);
            }
        }

        // mask
#pragma unroll
        for (int nj = 0; nj < 8; nj++) {
            int2 mk0 = *(const int2*)(mrow0 + mt + nj*8 + tg*2);
            int2 mk1 = *(const int2*)(mrow1 + mt + nj*8 + tg*2);
            if (!mk0.x) s[nj][0] = NEGV;
            if (!mk0.y) s[nj][1] = NEGV;
            if (!mk1.x) s[nj][2] = NEGV;
            if (!mk1.y) s[nj][3] = NEGV;
        }

        // online softmax (rows in 4 lanes: shfl over lanes 1,2)
        float tm0 = -INFINITY, tm1 = -INFINITY;
#pragma unroll
        for (int nj = 0; nj < 8; nj++) {
            tm0 = fmaxf(tm0, fmaxf(s[nj][0], s[nj][1]));
            tm1 = fmaxf(tm1, fmaxf(s[nj][2], s[nj][3]));
        }
        tm0 = fmaxf(tm0, __shfl_xor_sync(0xffffffffu, tm0, 1));
        tm0 = fmaxf(tm0, __shfl_xor_sync(0xffffffffu, tm0, 2));
        tm1 = fmaxf(tm1, __shfl_xor_sync(0xffffffffu, tm1, 1));
        tm1 = fmaxf(tm1, __shfl_xor_sync(0xffffffffu, tm1, 2));
        float mn0 = fmaxf(m0, tm0), mn1 = fmaxf(m1, tm1);
        float c0 = __expf(m0 - mn0), c1 = __expf(m1 - mn1);
        float ts0 = 0.f, ts1 = 0.f;
#pragma unroll
        for (int nj = 0; nj < 8; nj++) {
            s[nj][0] = __expf(s[nj][0] - mn0);
            s[nj][1] = __expf(s[nj][1] - mn0);
            s[nj][2] = __expf(s[nj][2] - mn1);
            s[nj][3] = __expf(s[nj][3] - mn1);
            ts0 += s[nj][0] + s[nj][1];
            ts1 += s[nj][2] + s[nj][3];
        }
        ts0 += __shfl_xor_sync(0xffffffffu, ts0, 1);
        ts0 += __shfl_xor_sync(0xffffffffu, ts0, 2);
        ts1 += __shfl_xor_sync(0xffffffffu, ts1, 1);
        ts1 += __shfl_xor_sync(0xffffffffu, ts1, 2);
        l0 = l0 * c0 + ts0; m0 = mn0;
        l1 = l1 * c1 + ts1; m1 = mn1;
#pragma unroll
        for (int nj = 0; nj < 8; nj++) {
            o[nj][0] *= c0; o[nj][1] *= c0;
            o[nj][2] *= c1; o[nj][3] *= c1;
        }

        // O += P @ V   (P = this thread's s[] regs, split on the fly)
#pragma unroll
        for (int st = 0; st < 4; st++) {
            uint32_t pah[4], pal[4];
            split2(s[2*st  ][0], s[2*st  ][1], pah[0], pal[0]);
            split2(s[2*st  ][2], s[2*st  ][3], pah[1], pal[1]);
            split2(s[2*st+1][0], s[2*st+1][1], pah[2], pal[2]);
            split2(s[2*st+1][2], s[2*st+1][3], pah[3], pal[3]);
#pragma unroll
            for (int nj = 0; nj < 8; nj++) {
                const int r = (nj*8 + g) * FPK + 8*st + 2*tg;
                uint2 hv = *(const uint2*)&Vhi[r];
                uint2 lv = *(const uint2*)&Vlo[r];
                uint32_t bhv[2] = {hv.x, hv.y}, blv[2] = {lv.x, lv.y};
                mma3(o[nj], pah, pal, bhv, blv);
            }
        }
    }

    // normalize + write X[b, n, h*64 + d]
    float inv0 = 1.f / l0, inv1 = 1.f / l1;
    float* X0 = g_X + ((size_t)b * SEQ_N + n0 + rb + g) * CH + h * HD;
    float* X1 = X0 + (size_t)8 * CH;
#pragma unroll
    for (int nj = 0; nj < 8; nj++) {
        *(float2*)(X0 + nj*8 + tg*2) = make_float2(o[nj][0]*inv0, o[nj][1]*inv0);
        *(float2*)(X1 + nj*8 + tg*2) = make_float2(o[nj][2]*inv1, o[nj][3]*inv1);
    }
}

// ---------------------------------------------------------------------------
extern "C" void kernel_launch(void* const* d_in, const int* in_sizes, int n_in,
                              void* d_out, int out_size)
{
    const float* q     = (const float*)d_in[0];   // [4,1024,768]
    const float* kv    = (const float*)d_in[1];   // [4,2048,768]
    const float* Wq    = (const float*)d_in[2];   // [768,768]
    const float* Wkv   = (const float*)d_in[3];   // [1536,768]
    const float* Wproj = (const float*)d_in[4];   // [768,768]
    const float* bproj = (const float*)d_in[5];   // [768]
    const int*   mask  = (const int*)d_in[6];     // [4,1,1024,2048]
    float* out = (float*)d_out;                   // [4,1024,768]

    // Q projection: rows = 4096, cols = 768
    gemm_bf<<<dim3(CH/64, (BB*SEQ_N)/128), 256>>>(q, Wq, 0, nullptr, nullptr);
    // KV projection: rows = 8192, cols = 1536
    gemm_bf<<<dim3((2*CH)/64, (BB*SEQ_M)/128), 256>>>(kv, Wkv, 1, nullptr, nullptr);
    // Fused masked-softmax attention
    flash_bf<<<dim3(SEQ_N/64, BB*NH), 128>>>(mask);
    // Output projection + bias
    gemm_bf<<<dim3(CH/64, (BB*SEQ_N)/128), 256>>>(nullptr, Wproj, 2, out, bproj);
}

// round 8
// speedup vs baseline: 2.0228x; 1.5559x over previous
#include <cuda_runtime.h>
#include <cuda_bf16.h>
#include <math.h>
#include <stdint.h>

// Problem constants
#define BB     4
#define SEQ_N  1024
#define SEQ_M  2048
#define CH     768
#define NH     12
#define HD     64
#define QSCALE 0.125f
#define NEGV   -9e15f

// Scratch (device globals: allocation-free rule)
__device__ __align__(256) float g_Qp[BB*NH*SEQ_N*HD];   // [B,H,N,d] pre-scaled
__device__ __align__(256) float g_K [BB*NH*SEQ_M*HD];   // [B,H,M,d]
__device__ __align__(256) float g_V [BB*NH*SEQ_M*HD];   // [B,H,M,d]
__device__ __align__(256) float g_X [BB*SEQ_N*CH];      // attention out [B,N,C]

// ---------------------------------------------------------------------------
// bf16 helpers. pack_bf2(x0,x1): x0 -> bits[15:0] (lower k), x1 -> bits[31:16].
// split2: 3xBF16 decomposition of a k-pair into (hi, lo) packed words.
// ---------------------------------------------------------------------------
__device__ __forceinline__ uint32_t pack_bf2(float x0, float x1) {
    uint32_t r;
    asm("cvt.rn.bf16x2.f32 %0, %1, %2;" : "=r"(r) : "f"(x1), "f"(x0));
    return r;
}
__device__ __forceinline__ void split2(float x0, float x1, uint32_t& hi, uint32_t& lo) {
    hi = pack_bf2(x0, x1);
    float h0 = __uint_as_float(hi << 16);
    float h1 = __uint_as_float(hi & 0xffff0000u);
    lo = pack_bf2(x0 - h0, x1 - h1);
}
__device__ __forceinline__ void mma16(float* c, const uint32_t* a, const uint32_t* b) {
    asm volatile(
        "mma.sync.aligned.m16n8k16.row.col.f32.bf16.bf16.f32 "
        "{%0,%1,%2,%3}, {%4,%5,%6,%7}, {%8,%9}, {%0,%1,%2,%3};"
        : "+f"(c[0]), "+f"(c[1]), "+f"(c[2]), "+f"(c[3])
        : "r"(a[0]), "r"(a[1]), "r"(a[2]), "r"(a[3]), "r"(b[0]), "r"(b[1]));
}
// c += ah*bh + ah*bl + al*bh
__device__ __forceinline__ void mma3(float* c, const uint32_t* ah, const uint32_t* al,
                                     const uint32_t* bh, const uint32_t* bl) {
    mma16(c, ah, bh);
    mma16(c, ah, bl);
    mma16(c, al, bh);
}

// ---------------------------------------------------------------------------
// Projection GEMM: out[r,o] = sum_k A[r,k]*W[o,k], K=768, BK=32 (2 k-steps),
// double-buffered smem, one barrier per iteration, reg prefetch.
// Block 128m x 64n, 8 warps (4m x 2n).
// smem layout: [buf][plane][(st*ROWS + row)*8 + w], pair-interleaved words
// (w(p) = 2*(p&3)+(p>>2)) -> fragment LDS.64 conflict-free (pair-pitch 4).
// mode 0: Q proj (*QSCALE -> g_Qp)  1: KV proj (-> g_K/g_V)  2: out proj (+bias)
// ---------------------------------------------------------------------------
__global__ __launch_bounds__(256, 2)
void gemm_bf(const float* __restrict__ Ain, const float* __restrict__ W,
             int mode, float* __restrict__ out, const float* __restrict__ bias)
{
    __shared__ uint32_t SA[2][2][2*128*8];   // 32 KB
    __shared__ uint32_t SW[2][2][2*64*8];    // 16 KB

    const int tid  = threadIdx.x;
    const int warp = tid >> 5, lane = tid & 31;
    const int wm = warp >> 1, wn = warp & 1;
    const int g  = lane >> 2, tg = lane & 3;
    const int rowBase = blockIdx.y * 128;
    const int oBase   = blockIdx.x * 64;
    const float* A = (mode == 2) ? g_X : Ain;

    // Loaders: A = 1 row x 16 k (one full k-step) per thread; W = 1 row x 8 k.
    const int ar = tid >> 1, sa = tid & 1;
    const int wr = tid >> 2, wh = tid & 3;
    const int sw = wh >> 1,  h2 = wh & 1;
    const float* aSrc = A + (size_t)(rowBase + ar) * CH + sa * 16;
    const float* wSrc = W + (size_t)(oBase + wr) * CH + wh * 8;
    const int abw = (sa * 128 + ar) * 8;      // A word base
    const int wbw = (sw * 64 + wr) * 8 + h2;  // W word base

    float4 pa0 = *(const float4*)(aSrc);
    float4 pa1 = *(const float4*)(aSrc + 4);
    float4 pa2 = *(const float4*)(aSrc + 8);
    float4 pa3 = *(const float4*)(aSrc + 12);
    float4 pw0 = *(const float4*)(wSrc);
    float4 pw1 = *(const float4*)(wSrc + 4);

    float acc[2][4][4];
#pragma unroll
    for (int mi = 0; mi < 2; mi++)
#pragma unroll
        for (int nj = 0; nj < 4; nj++)
#pragma unroll
            for (int t = 0; t < 4; t++) acc[mi][nj][t] = 0.f;

    // stage tile 0 into buffer 0
    {
        uint32_t h0,l0,h1,l1,h2_,l2_,h3,l3;
        split2(pa0.x, pa0.y, h0, l0); split2(pa2.x, pa2.y, h1, l1);
        split2(pa0.z, pa0.w, h2_, l2_); split2(pa2.z, pa2.w, h3, l3);
        *(uint4*)&SA[0][0][abw]     = make_uint4(h0, h1, h2_, h3);
        *(uint4*)&SA[0][1][abw]     = make_uint4(l0, l1, l2_, l3);
        split2(pa1.x, pa1.y, h0, l0); split2(pa3.x, pa3.y, h1, l1);
        split2(pa1.z, pa1.w, h2_, l2_); split2(pa3.z, pa3.w, h3, l3);
        *(uint4*)&SA[0][0][abw + 4] = make_uint4(h0, h1, h2_, h3);
        *(uint4*)&SA[0][1][abw + 4] = make_uint4(l0, l1, l2_, l3);
        uint32_t h, l;
        split2(pw0.x, pw0.y, h, l); SW[0][0][wbw  ] = h; SW[0][1][wbw  ] = l;
        split2(pw0.z, pw0.w, h, l); SW[0][0][wbw+2] = h; SW[0][1][wbw+2] = l;
        split2(pw1.x, pw1.y, h, l); SW[0][0][wbw+4] = h; SW[0][1][wbw+4] = l;
        split2(pw1.z, pw1.w, h, l); SW[0][0][wbw+6] = h; SW[0][1][wbw+6] = l;
    }
    __syncthreads();

    int buf = 0;
#pragma unroll 1
    for (int kt = 0; kt < CH; kt += 32) {
        const bool last = (kt + 32 >= CH);
        if (!last) {   // prefetch next tile (latency covered by compute below)
            pa0 = *(const float4*)(aSrc + kt + 32);
            pa1 = *(const float4*)(aSrc + kt + 36);
            pa2 = *(const float4*)(aSrc + kt + 40);
            pa3 = *(const float4*)(aSrc + kt + 44);
            pw0 = *(const float4*)(wSrc + kt + 32);
            pw1 = *(const float4*)(wSrc + kt + 36);
        }
        // compute current buffer: 2 k-steps
#pragma unroll
        for (int st = 0; st < 2; st++) {
            uint32_t Ah[2][4], Al[2][4];
#pragma unroll
            for (int mi = 0; mi < 2; mi++) {
                const int r = (st * 128 + wm * 32 + mi * 16 + g) * 8 + 2 * tg;
                uint2 h0 = *(const uint2*)&SA[buf][0][r];
                uint2 h1 = *(const uint2*)&SA[buf][0][r + 64];
                uint2 l0 = *(const uint2*)&SA[buf][1][r];
                uint2 l1 = *(const uint2*)&SA[buf][1][r + 64];
                Ah[mi][0] = h0.x; Ah[mi][1] = h1.x; Ah[mi][2] = h0.y; Ah[mi][3] = h1.y;
                Al[mi][0] = l0.x; Al[mi][1] = l1.x; Al[mi][2] = l0.y; Al[mi][3] = l1.y;
            }
            uint32_t Bh[4][2], Bl[4][2];
#pragma unroll
            for (int nj = 0; nj < 4; nj++) {
                const int r = (st * 64 + wn * 32 + nj * 8 + g) * 8 + 2 * tg;
                uint2 hv = *(const uint2*)&SW[buf][0][r];
                uint2 lv = *(const uint2*)&SW[buf][1][r];
                Bh[nj][0] = hv.x; Bh[nj][1] = hv.y;
                Bl[nj][0] = lv.x; Bl[nj][1] = lv.y;
            }
#pragma unroll
            for (int mi = 0; mi < 2; mi++)
#pragma unroll
                for (int nj = 0; nj < 4; nj++)
                    mma3(acc[mi][nj], Ah[mi], Al[mi], Bh[nj], Bl[nj]);
        }
        if (!last) {   // stage next tile into the other buffer
            const int nb = buf ^ 1;
            uint32_t h0,l0,h1,l1,h2_,l2_,h3,l3;
            split2(pa0.x, pa0.y, h0, l0); split2(pa2.x, pa2.y, h1, l1);
            split2(pa0.z, pa0.w, h2_, l2_); split2(pa2.z, pa2.w, h3, l3);
            *(uint4*)&SA[nb][0][abw]     = make_uint4(h0, h1, h2_, h3);
            *(uint4*)&SA[nb][1][abw]     = make_uint4(l0, l1, l2_, l3);
            split2(pa1.x, pa1.y, h0, l0); split2(pa3.x, pa3.y, h1, l1);
            split2(pa1.z, pa1.w, h2_, l2_); split2(pa3.z, pa3.w, h3, l3);
            *(uint4*)&SA[nb][0][abw + 4] = make_uint4(h0, h1, h2_, h3);
            *(uint4*)&SA[nb][1][abw + 4] = make_uint4(l0, l1, l2_, l3);
            uint32_t h, l;
            split2(pw0.x, pw0.y, h, l); SW[nb][0][wbw  ] = h; SW[nb][1][wbw  ] = l;
            split2(pw0.z, pw0.w, h, l); SW[nb][0][wbw+2] = h; SW[nb][1][wbw+2] = l;
            split2(pw1.x, pw1.y, h, l); SW[nb][0][wbw+4] = h; SW[nb][1][wbw+4] = l;
            split2(pw1.z, pw1.w, h, l); SW[nb][0][wbw+6] = h; SW[nb][1][wbw+6] = l;
            __syncthreads();
        }
        buf ^= 1;
    }

    // Epilogue
#pragma unroll
    for (int mi = 0; mi < 2; mi++) {
        const int r0 = rowBase + wm * 32 + mi * 16 + g;
        const int r1 = r0 + 8;
#pragma unroll
        for (int nj = 0; nj < 4; nj++) {
            float* cc = acc[mi][nj];
            const int colLoc = wn * 32 + nj * 8 + tg * 2;
            if (mode == 0) {
                const int h = blockIdx.x;
                const int b0 = r0 >> 10, n0_ = r0 & 1023;
                const int b1 = r1 >> 10, n1_ = r1 & 1023;
                *(float2*)&g_Qp[(((size_t)(b0*NH + h)*SEQ_N + n0_) << 6) + colLoc] =
                    make_float2(cc[0]*QSCALE, cc[1]*QSCALE);
                *(float2*)&g_Qp[(((size_t)(b1*NH + h)*SEQ_N + n1_) << 6) + colLoc] =
                    make_float2(cc[2]*QSCALE, cc[3]*QSCALE);
            } else if (mode == 1) {
                const int bx = blockIdx.x;
                float* dst = (bx >= NH) ? g_V : g_K;
                const int h = bx % NH;
                const int b0 = r0 >> 11, m0_ = r0 & 2047;
                const int b1 = r1 >> 11, m1_ = r1 & 2047;
                *(float2*)&dst[(((size_t)(b0*NH + h)*SEQ_M + m0_) << 6) + colLoc] =
                    make_float2(cc[0], cc[1]);
                *(float2*)&dst[(((size_t)(b1*NH + h)*SEQ_M + m1_) << 6) + colLoc] =
                    make_float2(cc[2], cc[3]);
            } else {
                const int col = oBase + colLoc;
                float2 bi = *(const float2*)(bias + col);
                *(float2*)&out[(size_t)r0 * CH + col] = make_float2(cc[0]+bi.x, cc[1]+bi.y);
                *(float2*)&out[(size_t)r1 * CH + col] = make_float2(cc[2]+bi.x, cc[3]+bi.y);
            }
        }
    }
}

// ---------------------------------------------------------------------------
// Flash attention, bf16 3x. 256 thr = 8 warps x 16 q-rows = 128 q-rows/block.
// Ks/Vs hi/lo planes, pitch FPK=40 words (pair-pitch 20 == 4 mod 16 ->
// fragment LDS.64 conflict-free). V transposed at staging (bf16 half stores).
// P stays in registers. grid = (N/128, B*H)
// ---------------------------------------------------------------------------
#define FPK 40

__global__ __launch_bounds__(256, 2)
void flash_bf(const int* __restrict__ mask)
{
    __shared__ uint32_t Khi[64*FPK], Klo[64*FPK];
    __shared__ uint32_t Vhi[64*FPK], Vlo[64*FPK];

    const int tid  = threadIdx.x;
    const int warp = tid >> 5, lane = tid & 31;
    const int g = lane >> 2, tg = lane & 3;
    const int bh = blockIdx.y, b = bh / NH, h = bh % NH;
    const int n0 = blockIdx.x * 128;
    const int rb = warp * 16;

    // Q fragments from gmem, split once into registers
    uint32_t qh[4][4], ql[4][4];
    {
        const float* Qr0 = g_Qp + ((size_t)bh * SEQ_N + n0 + rb + g) * HD;
        const float* Qr1 = Qr0 + 8 * HD;
#pragma unroll
        for (int s = 0; s < 4; s++) {
            float2 x0 = *(const float2*)(Qr0 + 16*s + 2*tg);
            float2 x1 = *(const float2*)(Qr1 + 16*s + 2*tg);
            float2 x2 = *(const float2*)(Qr0 + 16*s + 8 + 2*tg);
            float2 x3 = *(const float2*)(Qr1 + 16*s + 8 + 2*tg);
            split2(x0.x, x0.y, qh[s][0], ql[s][0]);
            split2(x1.x, x1.y, qh[s][1], ql[s][1]);
            split2(x2.x, x2.y, qh[s][2], ql[s][2]);
            split2(x3.x, x3.y, qh[s][3], ql[s][3]);
        }
    }

    float m0 = -INFINITY, m1 = -INFINITY, l0 = 0.f, l1 = 0.f;
    float o[8][4];
#pragma unroll
    for (int nj = 0; nj < 8; nj++)
#pragma unroll
        for (int t = 0; t < 4; t++) o[nj][t] = 0.f;

    // staging geometry: thread = (row m = tid>>2, d-step sq = tid&3)
    const int smr = tid >> 2, sq = tid & 3;
    const int pm  = (smr & 15) >> 1;
    const int wv  = 8 * (smr >> 4) + 2 * (pm & 3) + (pm >> 2);
    const int vhalf = smr & 1;
    const int kb = smr * FPK + 8 * sq;

    const int* mrow0 = mask + ((size_t)b * SEQ_N + n0 + rb + g) * SEQ_M;
    const int* mrow1 = mrow0 + (size_t)8 * SEQ_M;
    const float* Kg = g_K + (size_t)bh * SEQ_M * HD;
    const float* Vg = g_V + (size_t)bh * SEQ_M * HD;

#pragma unroll 1
    for (int mt = 0; mt < SEQ_M; mt += 64) {
        __syncthreads();   // previous PV reads done before overwrite
        {
            const float* krow = Kg + (size_t)(mt + smr) * HD + sq * 16;
            const float* vrow = Vg + (size_t)(mt + smr) * HD + sq * 16;
            float4 k0 = *(const float4*)(krow);
            float4 k1 = *(const float4*)(krow + 4);
            float4 k2 = *(const float4*)(krow + 8);
            float4 k3 = *(const float4*)(krow + 12);
            uint32_t h0,l0_,h1,l1_,h2_,l2_,h3,l3_;
            split2(k0.x, k0.y, h0, l0_); split2(k2.x, k2.y, h1, l1_);
            split2(k0.z, k0.w, h2_, l2_); split2(k2.z, k2.w, h3, l3_);
            *(uint4*)&Khi[kb]     = make_uint4(h0, h1, h2_, h3);
            *(uint4*)&Klo[kb]     = make_uint4(l0_, l1_, l2_, l3_);
            split2(k1.x, k1.y, h0, l0_); split2(k3.x, k3.y, h1, l1_);
            split2(k1.z, k1.w, h2_, l2_); split2(k3.z, k3.w, h3, l3_);
            *(uint4*)&Khi[kb + 4] = make_uint4(h0, h1, h2_, h3);
            *(uint4*)&Klo[kb + 4] = make_uint4(l0_, l1_, l2_, l3_);

            float4 vv[4];
            vv[0] = *(const float4*)(vrow);
            vv[1] = *(const float4*)(vrow + 4);
            vv[2] = *(const float4*)(vrow + 8);
            vv[3] = *(const float4*)(vrow + 12);
            const float* ve = &vv[0].x;
#pragma unroll
            for (int i = 0; i < 16; i++) {
                float x = ve[i];
                __nv_bfloat16 hb = __float2bfloat16(x);
                __nv_bfloat16 lb = __float2bfloat16(x - __bfloat162float(hb));
                const int idx = ((sq * 16 + i) * FPK + wv) * 2 + vhalf;
                ((__nv_bfloat16*)Vhi)[idx] = hb;
                ((__nv_bfloat16*)Vlo)[idx] = lb;
            }
        }
        __syncthreads();

        // S = Q @ K^T  (per warp: 16 rows x 64 cols)
        float s[8][4];
#pragma unroll
        for (int nj = 0; nj < 8; nj++)
#pragma unroll
            for (int t = 0; t < 4; t++) s[nj][t] = 0.f;

#pragma unroll
        for (int st = 0; st < 4; st++) {
#pragma unroll
            for (int nj = 0; nj < 8; nj++) {
                const int r = (nj*8 + g) * FPK + 8*st + 2*tg;
                uint2 hv = *(const uint2*)&Khi[r];
                uint2 lv = *(const uint2*)&Klo[r];
                uint32_t bhv[2] = {hv.x, hv.y}, blv[2] = {lv.x, lv.y};
                mma3(s[nj], qh[st], ql[st], bhv, blv);
            }
        }

        // mask
#pragma unroll
        for (int nj = 0; nj < 8; nj++) {
            int2 mk0 = *(const int2*)(mrow0 + mt + nj*8 + tg*2);
            int2 mk1 = *(const int2*)(mrow1 + mt + nj*8 + tg*2);
            if (!mk0.x) s[nj][0] = NEGV;
            if (!mk0.y) s[nj][1] = NEGV;
            if (!mk1.x) s[nj][2] = NEGV;
            if (!mk1.y) s[nj][3] = NEGV;
        }

        // online softmax (rows in 4 lanes: shfl over lanes 1,2)
        float tm0 = -INFINITY, tm1 = -INFINITY;
#pragma unroll
        for (int nj = 0; nj < 8; nj++) {
            tm0 = fmaxf(tm0, fmaxf(s[nj][0], s[nj][1]));
            tm1 = fmaxf(tm1, fmaxf(s[nj][2], s[nj][3]));
        }
        tm0 = fmaxf(tm0, __shfl_xor_sync(0xffffffffu, tm0, 1));
        tm0 = fmaxf(tm0, __shfl_xor_sync(0xffffffffu, tm0, 2));
        tm1 = fmaxf(tm1, __shfl_xor_sync(0xffffffffu, tm1, 1));
        tm1 = fmaxf(tm1, __shfl_xor_sync(0xffffffffu, tm1, 2));
        float mn0 = fmaxf(m0, tm0), mn1 = fmaxf(m1, tm1);
        float c0 = __expf(m0 - mn0), c1 = __expf(m1 - mn1);
        float ts0 = 0.f, ts1 = 0.f;
#pragma unroll
        for (int nj = 0; nj < 8; nj++) {
            s[nj][0] = __expf(s[nj][0] - mn0);
            s[nj][1] = __expf(s[nj][1] - mn0);
            s[nj][2] = __expf(s[nj][2] - mn1);
            s[nj][3] = __expf(s[nj][3] - mn1);
            ts0 += s[nj][0] + s[nj][1];
            ts1 += s[nj][2] + s[nj][3];
        }
        ts0 += __shfl_xor_sync(0xffffffffu, ts0, 1);
        ts0 += __shfl_xor_sync(0xffffffffu, ts0, 2);
        ts1 += __shfl_xor_sync(0xffffffffu, ts1, 1);
        ts1 += __shfl_xor_sync(0xffffffffu, ts1, 2);
        l0 = l0 * c0 + ts0; m0 = mn0;
        l1 = l1 * c1 + ts1; m1 = mn1;
#pragma unroll
        for (int nj = 0; nj < 8; nj++) {
            o[nj][0] *= c0; o[nj][1] *= c0;
            o[nj][2] *= c1; o[nj][3] *= c1;
        }

        // O += P @ V   (P = this thread's s[] regs, split on the fly)
#pragma unroll
        for (int st = 0; st < 4; st++) {
            uint32_t pah[4], pal[4];
            split2(s[2*st  ][0], s[2*st  ][1], pah[0], pal[0]);
            split2(s[2*st  ][2], s[2*st  ][3], pah[1], pal[1]);
            split2(s[2*st+1][0], s[2*st+1][1], pah[2], pal[2]);
            split2(s[2*st+1][2], s[2*st+1][3], pah[3], pal[3]);
#pragma unroll
            for (int nj = 0; nj < 8; nj++) {
                const int r = (nj*8 + g) * FPK + 8*st + 2*tg;
                uint2 hv = *(const uint2*)&Vhi[r];
                uint2 lv = *(const uint2*)&Vlo[r];
                uint32_t bhv[2] = {hv.x, hv.y}, blv[2] = {lv.x, lv.y};
                mma3(o[nj], pah, pal, bhv, blv);
            }
        }
    }

    // normalize + write X[b, n, h*64 + d]
    float inv0 = 1.f / l0, inv1 = 1.f / l1;
    float* X0 = g_X + ((size_t)b * SEQ_N + n0 + rb + g) * CH + h * HD;
    float* X1 = X0 + (size_t)8 * CH;
#pragma unroll
    for (int nj = 0; nj < 8; nj++) {
        *(float2*)(X0 + nj*8 + tg*2) = make_float2(o[nj][0]*inv0, o[nj][1]*inv0);
        *(float2*)(X1 + nj*8 + tg*2) = make_float2(o[nj][2]*inv1, o[nj][3]*inv1);
    }
}

// ---------------------------------------------------------------------------
extern "C" void kernel_launch(void* const* d_in, const int* in_sizes, int n_in,
                              void* d_out, int out_size)
{
    const float* q     = (const float*)d_in[0];   // [4,1024,768]
    const float* kv    = (const float*)d_in[1];   // [4,2048,768]
    const float* Wq    = (const float*)d_in[2];   // [768,768]
    const float* Wkv   = (const float*)d_in[3];   // [1536,768]
    const float* Wproj = (const float*)d_in[4];   // [768,768]
    const float* bproj = (const float*)d_in[5];   // [768]
    const int*   mask  = (const int*)d_in[6];     // [4,1,1024,2048]
    float* out = (float*)d_out;                   // [4,1024,768]

    // Q projection: rows = 4096, cols = 768
    gemm_bf<<<dim3(CH/64, (BB*SEQ_N)/128), 256>>>(q, Wq, 0, nullptr, nullptr);
    // KV projection: rows = 8192, cols = 1536
    gemm_bf<<<dim3((2*CH)/64, (BB*SEQ_M)/128), 256>>>(kv, Wkv, 1, nullptr, nullptr);
    // Fused masked-softmax attention
    flash_bf<<<dim3(SEQ_N/128, BB*NH), 256>>>(mask);
    // Output projection + bias
    gemm_bf<<<dim3(CH/64, (BB*SEQ_N)/128), 256>>>(nullptr, Wproj, 2, out, bproj);
}

// round 14
// speedup vs baseline: 2.1830x; 1.0792x over previous
#include <cuda_runtime.h>
#include <math.h>
#include <stdint.h>

// Problem constants
#define BB     4
#define SEQ_N  1024
#define SEQ_M  2048
#define CH     768
#define NH     12
#define HD     64
#define QSCALE 0.125f
#define NEGV   -9e15f

// Scratch (device globals: allocation-free rule)
__device__ __align__(256) float g_Qp[BB*NH*SEQ_N*HD];   // [B,H,N,d] pre-scaled
__device__ __align__(256) float g_K [BB*NH*SEQ_M*HD];   // [B,H,M,d]
__device__ __align__(256) float g_V [BB*NH*SEQ_M*HD];   // [B,H,M,d]
__device__ __align__(256) float g_X [BB*SEQ_N*CH];      // attention out [B,N,C]

// Pre-split bf16 hi/lo planes for flash (word = bf16x2 pair, interleaved
// within each 16-element step: w(p) = 2*(p&3) + (p>>2))
__device__ __align__(256) uint32_t pk_h [48*2048*32], pk_l [48*2048*32]; // K   [bh][m][dw]
__device__ __align__(256) uint32_t pvt_h[48*64*1024], pvt_l[48*64*1024]; // V^T [bh][d][mw]

// ---------------------------------------------------------------------------
__device__ __forceinline__ uint32_t pack_bf2(float x0, float x1) {
    uint32_t r;
    asm("cvt.rn.bf16x2.f32 %0, %1, %2;" : "=r"(r) : "f"(x1), "f"(x0));
    return r;
}
__device__ __forceinline__ void split2(float x0, float x1, uint32_t& hi, uint32_t& lo) {
    hi = pack_bf2(x0, x1);
    float h0 = __uint_as_float(hi << 16);
    float h1 = __uint_as_float(hi & 0xffff0000u);
    lo = pack_bf2(x0 - h0, x1 - h1);
}
__device__ __forceinline__ void mma16(float* c, const uint32_t* a, const uint32_t* b) {
    asm volatile(
        "mma.sync.aligned.m16n8k16.row.col.f32.bf16.bf16.f32 "
        "{%0,%1,%2,%3}, {%4,%5,%6,%7}, {%8,%9}, {%0,%1,%2,%3};"
        : "+f"(c[0]), "+f"(c[1]), "+f"(c[2]), "+f"(c[3])
        : "r"(a[0]), "r"(a[1]), "r"(a[2]), "r"(a[3]), "r"(b[0]), "r"(b[1]));
}
__device__ __forceinline__ void mma3(float* c, const uint32_t* ah, const uint32_t* al,
                                     const uint32_t* bh, const uint32_t* bl) {
    mma16(c, ah, bh);
    mma16(c, ah, bl);
    mma16(c, al, bh);
}
__device__ __forceinline__ void cp16(uint32_t dst, const void* src) {
    asm volatile("cp.async.cg.shared.global [%0], [%1], 16;" :: "r"(dst), "l"(src));
}
#define CP_COMMIT() asm volatile("cp.async.commit_group;")
#define CP_WAIT(n)  asm volatile("cp.async.wait_group %0;" :: "n"(n))

// ---------------------------------------------------------------------------
// Projection GEMM (R8-proven, verbatim): out[r,o] = sum_k A[r,k]*W[o,k],
// K=768, BK=32 (2 k-steps), double-buffered smem, reg prefetch, split at stage.
// Block 128m x 64n, 8 warps (4m x 2n).
// mode 0: Q proj (*QSCALE -> g_Qp)  1: KV proj (-> g_K/g_V)  2: out proj (+bias)
// ---------------------------------------------------------------------------
__global__ __launch_bounds__(256, 2)
void gemm_bf(const float* __restrict__ Ain, const float* __restrict__ W,
             int mode, float* __restrict__ out, const float* __restrict__ bias)
{
    __shared__ uint32_t SA[2][2][2*128*8];   // 32 KB
    __shared__ uint32_t SW[2][2][2*64*8];    // 16 KB

    const int tid  = threadIdx.x;
    const int warp = tid >> 5, lane = tid & 31;
    const int wm = warp >> 1, wn = warp & 1;
    const int g  = lane >> 2, tg = lane & 3;
    const int rowBase = blockIdx.y * 128;
    const int oBase   = blockIdx.x * 64;
    const float* A = (mode == 2) ? g_X : Ain;

    // Loaders: A = 1 row x 16 k (one full k-step) per thread; W = 1 row x 8 k.
    const int ar = tid >> 1, sa = tid & 1;
    const int wr = tid >> 2, wh = tid & 3;
    const int sw = wh >> 1,  h2 = wh & 1;
    const float* aSrc = A + (size_t)(rowBase + ar) * CH + sa * 16;
    const float* wSrc = W + (size_t)(oBase + wr) * CH + wh * 8;
    const int abw = (sa * 128 + ar) * 8;      // A word base
    const int wbw = (sw * 64 + wr) * 8 + h2;  // W word base

    float4 pa0 = *(const float4*)(aSrc);
    float4 pa1 = *(const float4*)(aSrc + 4);
    float4 pa2 = *(const float4*)(aSrc + 8);
    float4 pa3 = *(const float4*)(aSrc + 12);
    float4 pw0 = *(const float4*)(wSrc);
    float4 pw1 = *(const float4*)(wSrc + 4);

    float acc[2][4][4];
#pragma unroll
    for (int mi = 0; mi < 2; mi++)
#pragma unroll
        for (int nj = 0; nj < 4; nj++)
#pragma unroll
            for (int t = 0; t < 4; t++) acc[mi][nj][t] = 0.f;

    // stage tile 0 into buffer 0
    {
        uint32_t h0,l0,h1,l1,h2_,l2_,h3,l3;
        split2(pa0.x, pa0.y, h0, l0); split2(pa2.x, pa2.y, h1, l1);
        split2(pa0.z, pa0.w, h2_, l2_); split2(pa2.z, pa2.w, h3, l3);
        *(uint4*)&SA[0][0][abw]     = make_uint4(h0, h1, h2_, h3);
        *(uint4*)&SA[0][1][abw]     = make_uint4(l0, l1, l2_, l3);
        split2(pa1.x, pa1.y, h0, l0); split2(pa3.x, pa3.y, h1, l1);
        split2(pa1.z, pa1.w, h2_, l2_); split2(pa3.z, pa3.w, h3, l3);
        *(uint4*)&SA[0][0][abw + 4] = make_uint4(h0, h1, h2_, h3);
        *(uint4*)&SA[0][1][abw + 4] = make_uint4(l0, l1, l2_, l3);
        uint32_t h, l;
        split2(pw0.x, pw0.y, h, l); SW[0][0][wbw  ] = h; SW[0][1][wbw  ] = l;
        split2(pw0.z, pw0.w, h, l); SW[0][0][wbw+2] = h; SW[0][1][wbw+2] = l;
        split2(pw1.x, pw1.y, h, l); SW[0][0][wbw+4] = h; SW[0][1][wbw+4] = l;
        split2(pw1.z, pw1.w, h, l); SW[0][0][wbw+6] = h; SW[0][1][wbw+6] = l;
    }
    __syncthreads();

    int buf = 0;
#pragma unroll 1
    for (int kt = 0; kt < CH; kt += 32) {
        const bool last = (kt + 32 >= CH);
        if (!last) {   // prefetch next tile (latency covered by compute below)
            pa0 = *(const float4*)(aSrc + kt + 32);
            pa1 = *(const float4*)(aSrc + kt + 36);
            pa2 = *(const float4*)(aSrc + kt + 40);
            pa3 = *(const float4*)(aSrc + kt + 44);
            pw0 = *(const float4*)(wSrc + kt + 32);
            pw1 = *(const float4*)(wSrc + kt + 36);
        }
        // compute current buffer: 2 k-steps
#pragma unroll
        for (int st = 0; st < 2; st++) {
            uint32_t Ah[2][4], Al[2][4];
#pragma unroll
            for (int mi = 0; mi < 2; mi++) {
                const int r = (st * 128 + wm * 32 + mi * 16 + g) * 8 + 2 * tg;
                uint2 h0 = *(const uint2*)&SA[buf][0][r];
                uint2 h1 = *(const uint2*)&SA[buf][0][r + 64];
                uint2 l0 = *(const uint2*)&SA[buf][1][r];
                uint2 l1 = *(const uint2*)&SA[buf][1][r + 64];
                Ah[mi][0] = h0.x; Ah[mi][1] = h1.x; Ah[mi][2] = h0.y; Ah[mi][3] = h1.y;
                Al[mi][0] = l0.x; Al[mi][1] = l1.x; Al[mi][2] = l0.y; Al[mi][3] = l1.y;
            }
            uint32_t Bh[4][2], Bl[4][2];
#pragma unroll
            for (int nj = 0; nj < 4; nj++) {
                const int r = (st * 64 + wn * 32 + nj * 8 + g) * 8 + 2 * tg;
                uint2 hv = *(const uint2*)&SW[buf][0][r];
                uint2 lv = *(const uint2*)&SW[buf][1][r];
                Bh[nj][0] = hv.x; Bh[nj][1] = hv.y;
                Bl[nj][0] = lv.x; Bl[nj][1] = lv.y;
            }
#pragma unroll
            for (int mi = 0; mi < 2; mi++)
#pragma unroll
                for (int nj = 0; nj < 4; nj++)
                    mma3(acc[mi][nj], Ah[mi], Al[mi], Bh[nj], Bl[nj]);
        }
        if (!last) {   // stage next tile into the other buffer
            const int nb = buf ^ 1;
            uint32_t h0,l0,h1,l1,h2_,l2_,h3,l3;
            split2(pa0.x, pa0.y, h0, l0); split2(pa2.x, pa2.y, h1, l1);
            split2(pa0.z, pa0.w, h2_, l2_); split2(pa2.z, pa2.w, h3, l3);
            *(uint4*)&SA[nb][0][abw]     = make_uint4(h0, h1, h2_, h3);
            *(uint4*)&SA[nb][1][abw]     = make_uint4(l0, l1, l2_, l3);
            split2(pa1.x, pa1.y, h0, l0); split2(pa3.x, pa3.y, h1, l1);
            split2(pa1.z, pa1.w, h2_, l2_); split2(pa3.z, pa3.w, h3, l3);
            *(uint4*)&SA[nb][0][abw + 4] = make_uint4(h0, h1, h2_, h3);
            *(uint4*)&SA[nb][1][abw + 4] = make_uint4(l0, l1, l2_, l3);
            uint32_t h, l;
            split2(pw0.x, pw0.y, h, l); SW[nb][0][wbw  ] = h; SW[nb][1][wbw  ] = l;
            split2(pw0.z, pw0.w, h, l); SW[nb][0][wbw+2] = h; SW[nb][1][wbw+2] = l;
            split2(pw1.x, pw1.y, h, l); SW[nb][0][wbw+4] = h; SW[nb][1][wbw+4] = l;
            split2(pw1.z, pw1.w, h, l); SW[nb][0][wbw+6] = h; SW[nb][1][wbw+6] = l;
            __syncthreads();
        }
        buf ^= 1;
    }

    // Epilogue (R8 verbatim)
#pragma unroll
    for (int mi = 0; mi < 2; mi++) {
        const int r0 = rowBase + wm * 32 + mi * 16 + g;
        const int r1 = r0 + 8;
#pragma unroll
        for (int nj = 0; nj < 4; nj++) {
            float* cc = acc[mi][nj];
            const int colLoc = wn * 32 + nj * 8 + tg * 2;
            if (mode == 0) {
                const int h = blockIdx.x;
                const int b0 = r0 >> 10, n0_ = r0 & 1023;
                const int b1 = r1 >> 10, n1_ = r1 & 1023;
                *(float2*)&g_Qp[(((size_t)(b0*NH + h)*SEQ_N + n0_) << 6) + colLoc] =
                    make_float2(cc[0]*QSCALE, cc[1]*QSCALE);
                *(float2*)&g_Qp[(((size_t)(b1*NH + h)*SEQ_N + n1_) << 6) + colLoc] =
                    make_float2(cc[2]*QSCALE, cc[3]*QSCALE);
            } else if (mode == 1) {
                const int bx = blockIdx.x;
                float* dst = (bx >= NH) ? g_V : g_K;
                const int h = bx % NH;
                const int b0 = r0 >> 11, m0_ = r0 & 2047;
                const int b1 = r1 >> 11, m1_ = r1 & 2047;
                *(float2*)&dst[(((size_t)(b0*NH + h)*SEQ_M + m0_) << 6) + colLoc] =
                    make_float2(cc[0], cc[1]);
                *(float2*)&dst[(((size_t)(b1*NH + h)*SEQ_M + m1_) << 6) + colLoc] =
                    make_float2(cc[2], cc[3]);
            } else {
                const int col = oBase + colLoc;
                float2 bi = *(const float2*)(bias + col);
                *(float2*)&out[(size_t)r0 * CH + col] = make_float2(cc[0]+bi.x, cc[1]+bi.y);
                *(float2*)&out[(size_t)r1 * CH + col] = make_float2(cc[2]+bi.x, cc[3]+bi.y);
            }
        }
    }
}

// ---------------------------------------------------------------------------
// K converter: g_K fp32 [bh][m][64] -> pk planes [bh][m][32 words],
// word w: step st = w>>3, wi = w&7, pair p = (wi>>1) + 4*(wi&1), d = 16st+2p.
// One thread per word; a warp covers exactly one K row (fully coalesced).
// ---------------------------------------------------------------------------
__global__ void kconv()
{
    int idx = blockIdx.x * blockDim.x + threadIdx.x;
    if (idx >= 48*2048*32) return;
    const int row = idx >> 5, w = idx & 31;
    const int wi = w & 7;
    const int p  = (wi >> 1) + ((wi & 1) << 2);
    const int d  = ((w >> 3) << 4) + 2 * p;
    float2 v = *(const float2*)(g_K + (size_t)row * HD + d);
    uint32_t h, l; split2(v.x, v.y, h, l);
    pk_h[idx] = h; pk_l[idx] = l;
}

// ---------------------------------------------------------------------------
// V converter (transposing): g_V fp32 [bh][m][64] -> pvt planes [bh][d][1024],
// word mw: m-step stg = mw>>3, wi = mw&7, pair p as above, m = 16*stg + 2p,
// lower half = V[m][d], upper = V[m+1][d].
// Block = one (bh, 16-m step): stage 16x64 tile in smem, write coalesced.
// NOTE: tile pitch 68 floats (272 B == 0 mod 16) -- pitch 65 trapped with
// "misaligned address" on the float4 stores (R12).
// ---------------------------------------------------------------------------
__global__ __launch_bounds__(256)
void vconv()
{
    __shared__ float vs[16][68];
    const int bid = blockIdx.x;            // [0, 48*128)
    const int bh = bid >> 7, stg = bid & 127;
    const int m0 = stg * 16;
    const int t = threadIdx.x;

    const int r = t >> 4, c4 = (t & 15) * 4;
    *(float4*)&vs[r][c4] =
        *(const float4*)(g_V + ((size_t)bh * SEQ_M + m0 + r) * HD + c4);
    __syncthreads();

#pragma unroll
    for (int id = t; id < 512; id += 256) {
        const int d = id >> 3, wi = id & 7;
        const int p = (wi >> 1) + ((wi & 1) << 2);
        uint32_t h, l; split2(vs[2*p][d], vs[2*p + 1][d], h, l);
        const size_t o = ((size_t)bh * HD + d) * 1024 + stg * 8 + wi;
        pvt_h[o] = h; pvt_l[o] = l;
    }
}

// ---------------------------------------------------------------------------
// Flash attention. 256 thr = 8 warps x 16 q-rows = 128 q-rows/block.
// K/V tiles cp.async-staged from pre-split planes, double-buffered.
// Smem per buffer: Khi, Klo, Vhi, Vlo planes, pitch FPK=40 words.
// Q from fp32 g_Qp (split once in regs); epilogue writes fp32 g_X.
// grid = (N/128, B*H); dynamic smem 80 KB.
// ---------------------------------------------------------------------------
#define FPK 40
#define PLW (64*FPK)                       // 2560 words per plane
#define FA_SMEM (2 * 4 * PLW * 4)          // 81920 B

__global__ __launch_bounds__(256)
void flash_bf(const int* __restrict__ mask)
{
    extern __shared__ uint32_t sm[];
    const int tid  = threadIdx.x;
    const int warp = tid >> 5, lane = tid & 31;
    const int g = lane >> 2, tg = lane & 3;
    const int bh = blockIdx.y, b = bh / NH, h = bh % NH;
    const int n0 = blockIdx.x * 128;
    const int rb = warp * 16;

    const uint32_t smBase = (uint32_t)__cvta_generic_to_shared(sm);

    // Q fragments from fp32 g_Qp, split once into registers (R8-proven path)
    uint32_t qh[4][4], ql[4][4];
    {
        const float* Qr0 = g_Qp + ((size_t)bh * SEQ_N + n0 + rb + g) * HD;
        const float* Qr1 = Qr0 + 8 * HD;
#pragma unroll
        for (int s = 0; s < 4; s++) {
            float2 x0 = *(const float2*)(Qr0 + 16*s + 2*tg);
            float2 x1 = *(const float2*)(Qr1 + 16*s + 2*tg);
            float2 x2 = *(const float2*)(Qr0 + 16*s + 8 + 2*tg);
            float2 x3 = *(const float2*)(Qr1 + 16*s + 8 + 2*tg);
            split2(x0.x, x0.y, qh[s][0], ql[s][0]);
            split2(x1.x, x1.y, qh[s][1], ql[s][1]);
            split2(x2.x, x2.y, qh[s][2], ql[s][2]);
            split2(x3.x, x3.y, qh[s][3], ql[s][3]);
        }
    }

    float m0 = -INFINITY, m1 = -INFINITY, l0 = 0.f, l1 = 0.f;
    float o[8][4];
#pragma unroll
    for (int nj = 0; nj < 8; nj++)
#pragma unroll
        for (int t = 0; t < 4; t++) o[nj][t] = 0.f;

    const int* mrow0 = mask + ((size_t)b * SEQ_N + n0 + rb + g) * SEQ_M;
    const int* mrow1 = mrow0 + (size_t)8 * SEQ_M;
    const uint32_t* pkh = pk_h + (size_t)bh * SEQ_M * 32;
    const uint32_t* pkl = pk_l + (size_t)bh * SEQ_M * 32;
    const uint32_t* pvh = pvt_h + (size_t)bh * HD * 1024;
    const uint32_t* pvl = pvt_l + (size_t)bh * HD * 1024;

#define FLASH_STAGE(MT, BUF)                                                            \
    {                                                                                   \
        const uint32_t kb = smBase + (BUF) * 4 * PLW * 4;                               \
        _Pragma("unroll")                                                               \
        for (int j = 0; j < 4; j++) {                                                   \
            int aid = tid + j * 256;                                                    \
            int ch = aid & 1, st = (aid >> 1) & 3, row = (aid >> 3) & 63, pl = aid >> 9;\
            const uint32_t* s_ = (pl ? pkl : pkh)                                       \
                + (size_t)((MT) + row) * 32 + st * 8 + ch * 4;                          \
            cp16(kb + (pl * PLW + row * FPK + st * 8 + ch * 4) * 4, s_);                \
        }                                                                               \
        _Pragma("unroll")                                                               \
        for (int j = 0; j < 4; j++) {                                                   \
            int vd = tid + j * 256;                                                     \
            int ch = vd & 7, d = (vd >> 3) & 63, pl = vd >> 9;                          \
            const uint32_t* s_ = (pl ? pvl : pvh)                                       \
                + (size_t)d * 1024 + ((MT) >> 1) + ch * 4;                              \
            cp16(kb + ((2 + pl) * PLW + d * FPK + ch * 4) * 4, s_);                     \
        }                                                                               \
        CP_COMMIT();                                                                    \
    }

    FLASH_STAGE(0, 0);
    int buf = 0;
#pragma unroll 1
    for (int mt = 0; mt < SEQ_M; mt += 64) {
        __syncthreads();
        if (mt + 64 < SEQ_M) { FLASH_STAGE(mt + 64, buf ^ 1); CP_WAIT(1); }
        else                 { CP_WAIT(0); }
        __syncthreads();
        const uint32_t* Khi = sm + buf * 4 * PLW;
        const uint32_t* Klo = Khi + PLW;
        const uint32_t* Vhi = Khi + 2 * PLW;
        const uint32_t* Vlo = Khi + 3 * PLW;

        // S = Q @ K^T  (per warp: 16 rows x 64 cols)
        float s[8][4];
#pragma unroll
        for (int nj = 0; nj < 8; nj++)
#pragma unroll
            for (int t = 0; t < 4; t++) s[nj][t] = 0.f;
#pragma unroll
        for (int st = 0; st < 4; st++) {
#pragma unroll
            for (int nj = 0; nj < 8; nj++) {
                const int r = (nj * 8 + g) * FPK + 8 * st + 2 * tg;
                uint2 hv = *(const uint2*)&Khi[r];
                uint2 lv = *(const uint2*)&Klo[r];
                uint32_t bhv[2] = {hv.x, hv.y}, blv[2] = {lv.x, lv.y};
                mma3(s[nj], qh[st], ql[st], bhv, blv);
            }
        }

        // mask
#pragma unroll
        for (int nj = 0; nj < 8; nj++) {
            int2 mk0 = *(const int2*)(mrow0 + mt + nj * 8 + tg * 2);
            int2 mk1 = *(const int2*)(mrow1 + mt + nj * 8 + tg * 2);
            if (!mk0.x) s[nj][0] = NEGV;
            if (!mk0.y) s[nj][1] = NEGV;
            if (!mk1.x) s[nj][2] = NEGV;
            if (!mk1.y) s[nj][3] = NEGV;
        }

        // online softmax (rows in 4 lanes: shfl over lanes 1,2)
        float tm0 = -INFINITY, tm1 = -INFINITY;
#pragma unroll
        for (int nj = 0; nj < 8; nj++) {
            tm0 = fmaxf(tm0, fmaxf(s[nj][0], s[nj][1]));
            tm1 = fmaxf(tm1, fmaxf(s[nj][2], s[nj][3]));
        }
        tm0 = fmaxf(tm0, __shfl_xor_sync(0xffffffffu, tm0, 1));
        tm0 = fmaxf(tm0, __shfl_xor_sync(0xffffffffu, tm0, 2));
        tm1 = fmaxf(tm1, __shfl_xor_sync(0xffffffffu, tm1, 1));
        tm1 = fmaxf(tm1, __shfl_xor_sync(0xffffffffu, tm1, 2));
        float mn0 = fmaxf(m0, tm0), mn1 = fmaxf(m1, tm1);
        float c0 = __expf(m0 - mn0), c1 = __expf(m1 - mn1);
        float ts0 = 0.f, ts1 = 0.f;
#pragma unroll
        for (int nj = 0; nj < 8; nj++) {
            s[nj][0] = __expf(s[nj][0] - mn0);
            s[nj][1] = __expf(s[nj][1] - mn0);
            s[nj][2] = __expf(s[nj][2] - mn1);
            s[nj][3] = __expf(s[nj][3] - mn1);
            ts0 += s[nj][0] + s[nj][1];
            ts1 += s[nj][2] + s[nj][3];
        }
        ts0 += __shfl_xor_sync(0xffffffffu, ts0, 1);
        ts0 += __shfl_xor_sync(0xffffffffu, ts0, 2);
        ts1 += __shfl_xor_sync(0xffffffffu, ts1, 1);
        ts1 += __shfl_xor_sync(0xffffffffu, ts1, 2);
        l0 = l0 * c0 + ts0; m0 = mn0;
        l1 = l1 * c1 + ts1; m1 = mn1;
#pragma unroll
        for (int nj = 0; nj < 8; nj++) {
            o[nj][0] *= c0; o[nj][1] *= c0;
            o[nj][2] *= c1; o[nj][3] *= c1;
        }

        // O += P @ V  (P split on the fly from regs)
#pragma unroll
        for (int st = 0; st < 4; st++) {
            uint32_t pah[4], pal[4];
            split2(s[2*st  ][0], s[2*st  ][1], pah[0], pal[0]);
            split2(s[2*st  ][2], s[2*st  ][3], pah[1], pal[1]);
            split2(s[2*st+1][0], s[2*st+1][1], pah[2], pal[2]);
            split2(s[2*st+1][2], s[2*st+1][3], pah[3], pal[3]);
#pragma unroll
            for (int nj = 0; nj < 8; nj++) {
                const int r = (nj * 8 + g) * FPK + 8 * st + 2 * tg;
                uint2 hv = *(const uint2*)&Vhi[r];
                uint2 lv = *(const uint2*)&Vlo[r];
                uint32_t bhv[2] = {hv.x, hv.y}, blv[2] = {lv.x, lv.y};
                mma3(o[nj], pah, pal, bhv, blv);
            }
        }
        buf ^= 1;
    }

    // normalize + write X[b, n, h*64 + d]  (R8 verbatim)
    float inv0 = 1.f / l0, inv1 = 1.f / l1;
    float* X0 = g_X + ((size_t)b * SEQ_N + n0 + rb + g) * CH + h * HD;
    float* X1 = X0 + (size_t)8 * CH;
#pragma unroll
    for (int nj = 0; nj < 8; nj++) {
        *(float2*)(X0 + nj*8 + tg*2) = make_float2(o[nj][0]*inv0, o[nj][1]*inv0);
        *(float2*)(X1 + nj*8 + tg*2) = make_float2(o[nj][2]*inv1, o[nj][3]*inv1);
    }
}

// ---------------------------------------------------------------------------
extern "C" void kernel_launch(void* const* d_in, const int* in_sizes, int n_in,
                              void* d_out, int out_size)
{
    const float* q     = (const float*)d_in[0];   // [4,1024,768]
    const float* kv    = (const float*)d_in[1];   // [4,2048,768]
    const float* Wq    = (const float*)d_in[2];   // [768,768]
    const float* Wkv   = (const float*)d_in[3];   // [1536,768]
    const float* Wproj = (const float*)d_in[4];   // [768,768]
    const float* bproj = (const float*)d_in[5];   // [768]
    const int*   mask  = (const int*)d_in[6];     // [4,1,1024,2048]
    float* out = (float*)d_out;                   // [4,1024,768]

    cudaFuncSetAttribute(flash_bf,
                         cudaFuncAttributeMaxDynamicSharedMemorySize, FA_SMEM);

    // Q projection: rows = 4096, cols = 768
    gemm_bf<<<dim3(CH/64, (BB*SEQ_N)/128), 256>>>(q, Wq, 0, nullptr, nullptr);
    // KV projection: rows = 8192, cols = 1536
    gemm_bf<<<dim3((2*CH)/64, (BB*SEQ_M)/128), 256>>>(kv, Wkv, 1, nullptr, nullptr);
    // Convert K/V to pre-split planes for flash
    kconv<<<(48*2048*32) / 256, 256>>>();
    vconv<<<48*128, 256>>>();
    // Fused masked-softmax attention
    flash_bf<<<dim3(SEQ_N/128, BB*NH), 256, FA_SMEM>>>(mask);
    // Output projection + bias
    gemm_bf<<<dim3(CH/64, (BB*SEQ_N)/128), 256>>>(nullptr, Wproj, 2, out, bproj);
}